// round 10
// baseline (speedup 1.0000x reference)
#include <cuda_runtime.h>
#include <cstdint>

#define G    8192
#define P    24
#define NN   (G*P)          // 196608
#define EE   (NN*4)         // 786432
#define FIN  74
#define H1   32
#define H2   8
#define CAP  152            // per-group compact edge capacity
#define BCAP 32             // per-node bucket capacity
#define EPSBN 1e-5f

// ---------------- scratch ----------------
__device__ int      g_ndeg[NN];                    // zero-init; kC resets
__device__ unsigned g_bucket[(size_t)NN * BCAP];   // eid | s_loc<<20
__device__ unsigned g_csr[G * CAP];
__device__ int      g_gm[G];
__device__ float    g_xl[(size_t)NN * H1];
__device__ float    g_xr[(size_t)NN * H1];
__device__ float    g_a1[(size_t)EE * H1];         // ea@We1, edge order
__device__ float    g_a2[(size_t)EE * H2];         // ea@We2, edge order
__device__ float    g_h1[(size_t)NN * H1];
__device__ float    g_h2[(size_t)NN * H2];
__device__ double   g_sum1[H1], g_sq1[H1], g_sum2[H2], g_sq2[H2]; // zero-init; kReset

// ---------------- K1: scatter into per-dst-node buckets ----------------
__global__ void kScatter(const int* __restrict__ ei) {
    int e = blockIdx.x * blockDim.x + threadIdx.x;
    if (e >= EE) return;
    int s = ei[e], d = ei[EE + e];
    int pos = atomicAdd(&g_ndeg[d], 1);
    if (pos < BCAP)
        g_bucket[(size_t)d * BCAP + pos] = (unsigned)e | ((unsigned)(s % P) << 20);
}

// ============ dense node GEMV — float4 k-blocked ============
__global__ __launch_bounds__(256) void kXlXr(
    const float* __restrict__ x,
    const float* __restrict__ Wl1, const float* __restrict__ bl1,
    const float* __restrict__ Wr1, const float* __restrict__ br1)
{
    __shared__ float2 sW[FIN * H1];
    __shared__ float  sx[64 * 76];
    int t = threadIdx.x, lane = t & 31, wid = t >> 5;
    int n0 = blockIdx.x * 64;

    for (int i = t; i < FIN * H1; i += 256)
        sW[i] = make_float2(Wl1[i], Wr1[i]);
    for (int i = t; i < 64 * 19; i += 256) {
        int r = i / 19, q = i - r * 19;
        ((float4*)(sx + r * 76))[q] = ((const float4*)(x + (size_t)(n0 + r) * 96))[q];
    }
    __syncthreads();

    float bl = bl1[lane], br = br1[lane];
    float al[8], ar[8];
#pragma unroll
    for (int n = 0; n < 8; n++) { al[n] = bl; ar[n] = br; }

    const float* xbase = sx + wid * 8 * 76;
#pragma unroll 1
    for (int k4 = 0; k4 < 18; k4++) {
        int k = k4 * 4;
        float2 w0 = sW[(k + 0) * H1 + lane];
        float2 w1 = sW[(k + 1) * H1 + lane];
        float2 w2 = sW[(k + 2) * H1 + lane];
        float2 w3 = sW[(k + 3) * H1 + lane];
#pragma unroll
        for (int n = 0; n < 8; n++) {
            float4 xv = *(const float4*)(xbase + n * 76 + k);
            al[n] += xv.x * w0.x + xv.y * w1.x + xv.z * w2.x + xv.w * w3.x;
            ar[n] += xv.x * w0.y + xv.y * w1.y + xv.z * w2.y + xv.w * w3.y;
        }
    }
    {
        float2 w0 = sW[72 * H1 + lane];
        float2 w1 = sW[73 * H1 + lane];
#pragma unroll
        for (int n = 0; n < 8; n++) {
            float2 xv = *(const float2*)(xbase + n * 76 + 72);
            al[n] += xv.x * w0.x + xv.y * w1.x;
            ar[n] += xv.x * w0.y + xv.y * w1.y;
        }
    }
#pragma unroll
    for (int n = 0; n < 8; n++) {
        size_t idx = (size_t)(n0 + wid * 8 + n) * H1 + lane;
        g_xl[idx] = al[n];
        g_xr[idx] = ar[n];
    }
}

// ============ dense edge GEMM: a1 = ea@We1, a2 = ea@We2 (edge order) ======
__global__ __launch_bounds__(256) void kA1A2(
    const float* __restrict__ ea,
    const float* __restrict__ We1, const float* __restrict__ We2)
{
    __shared__ float sea[128 * 16];
    __shared__ float sW[16 * 40];     // [k][40]: cols 0..31 We1, 32..39 We2
    int t = threadIdx.x;
    int e0 = blockIdx.x * 128;

    for (int i = t; i < 512; i += 256)
        ((float4*)sea)[i] = ((const float4*)ea)[(size_t)e0 * 4 + i];
    for (int i = t; i < 16 * 40; i += 256) {
        int k = i / 40, o = i - k * 40;
        sW[i] = (o < 32) ? We1[k * 32 + o] : We2[k * 8 + (o - 32)];
    }
    __syncthreads();

    int e = t >> 1, h = t & 1;            // 2 threads/edge, 5 output-quads each
    const float4* W4 = (const float4*)sW; // [k][10] quads
    float4 acc[5];
#pragma unroll
    for (int c = 0; c < 5; c++) acc[c] = make_float4(0.f, 0.f, 0.f, 0.f);
#pragma unroll
    for (int k = 0; k < 16; k++) {
        float evk = sea[e * 16 + k];
#pragma unroll
        for (int c = 0; c < 5; c++) {
            float4 w = W4[k * 10 + h * 5 + c];
            acc[c].x += evk * w.x; acc[c].y += evk * w.y;
            acc[c].z += evk * w.z; acc[c].w += evk * w.w;
        }
    }
    size_t eg = e0 + e;
#pragma unroll
    for (int c = 0; c < 5; c++) {
        int q = h * 5 + c;
        if (q < 8) ((float4*)g_a1)[eg * 8 + q] = acc[c];
        else       ((float4*)g_a2)[eg * 2 + (q - 8)] = acc[c];
    }
}

// ============ K2: GATv2 layer 1 — gather a1, logit+softmax+aggregate ======
__global__ __launch_bounds__(256, 6) void kA(
    const float* __restrict__ att1, const float* __restrict__ bo1)
{
    int g = blockIdx.x;
    int t = threadIdx.x, lane = t & 31, wid = t >> 5;

    __shared__ float satt[H1], sbo[H1];
    __shared__ float sxl[P * 36], sxr[P * 36];
    __shared__ float sa1[CAP * 32];             // gathered a1 rows (CSR order)
    __shared__ float se[CAP];
    __shared__ unsigned scsr[CAP];
    __shared__ int sdegc[P], sstart[P], sm_m[1];
    __shared__ float sred[256];

    // ---- phase 1: loads
    if (t < H1) { satt[t] = att1[t]; sbo[t] = bo1[t]; }
    for (int i = t; i < P * H1 / 4; i += 256) {
        int n = i >> 3, q = i & 7;
        ((float4*)(sxl + n * 36))[q] = ((const float4*)(g_xl + (size_t)g * P * H1))[i];
        ((float4*)(sxr + n * 36))[q] = ((const float4*)(g_xr + (size_t)g * P * H1))[i];
    }
    if (t < P) {
        int d = g_ndeg[g * P + t];
        sdegc[t] = d > BCAP ? BCAP : d;
    }
    __syncthreads();

    // ---- phase 2: warp-scan CSR starts
    if (wid == 0) {
        int v = (lane < P) ? sdegc[lane] : 0;
        int orig = v;
#pragma unroll
        for (int off = 1; off < 32; off <<= 1) {
            int u = __shfl_up_sync(0xffffffffu, v, off);
            if (lane >= off) v += u;
        }
        if (lane < P) sstart[lane] = v - orig;
        if (lane == P - 1) { sm_m[0] = v; g_gm[g] = v; }
    }
    __syncthreads();

    int base = g * CAP;
    int m = sm_m[0]; if (m > CAP) m = CAP;

    // ---- phase 3: compact copy from node buckets
    for (int n = wid; n < P; n += 8) {
        int deg = sdegc[n], st = sstart[n];
        if (lane < deg) {
            unsigned pk = g_bucket[(size_t)(g * P + n) * BCAP + lane]
                        | ((unsigned)n << 25);
            scsr[st + lane] = pk;
            g_csr[base + st + lane] = pk;
        }
    }
    __syncthreads();

    // ---- phase 4: gather a1 rows (128B each, fully used)
    for (int idx = t; idx < m * 8; idx += 256) {
        int j = idx >> 3, q = idx & 7;
        int eid = scsr[j] & 0xFFFFF;
        ((float4*)sa1)[j * 8 + q] = ((const float4*)g_a1)[(size_t)eid * 8 + q];
    }
    __syncthreads();

    // ---- phase 5: logits, thread-per-(edge, quad)
    {
        int oq = t & 7;
        unsigned omask = 0xFFu << ((lane >> 3) * 8);
        for (int j0 = 0; j0 < m; j0 += 32) {
            int j = j0 + (t >> 3);
            if (j < m) {
                unsigned pk = scsr[j];
                int s = (pk >> 20) & 31, d = (pk >> 25) & 31;
                float4 a   = *(const float4*)(sa1 + j * 32 + oq * 4);
                float4 xlv = *(const float4*)(sxl + s * 36 + oq * 4);
                float4 xrv = *(const float4*)(sxr + d * 36 + oq * 4);
                float4 atv = *(const float4*)(satt + oq * 4);
                float m0 = xlv.x + xrv.x + a.x, m1 = xlv.y + xrv.y + a.y;
                float m2 = xlv.z + xrv.z + a.z, m3 = xlv.w + xrv.w + a.w;
                float e = (m0 > 0.f ? m0 : 0.2f * m0) * atv.x
                        + (m1 > 0.f ? m1 : 0.2f * m1) * atv.y
                        + (m2 > 0.f ? m2 : 0.2f * m2) * atv.z
                        + (m3 > 0.f ? m3 : 0.2f * m3) * atv.w;
                e += __shfl_xor_sync(omask, e, 1);
                e += __shfl_xor_sync(omask, e, 2);
                e += __shfl_xor_sync(omask, e, 4);
                if (oq == 0) se[j] = e;
            }
        }
    }
    __syncthreads();

    // ---- phase 6: per-node softmax + aggregation (warp per node)
    float st_s = 0.f, st_q = 0.f;
    for (int n = wid; n < P; n += 8) {
        int st = sstart[n], deg = sdegc[n];
        float invd = 1.f / fmaxf((float)deg, 1.f);
        float xln = sxl[n * 36 + lane], xrn = sxr[n * 36 + lane];
        // sum1 = Σ_j a1_j  (linearity: == (Σ ea)@We1)
        float sum1 = 0.f;
        for (int j = st; j < st + deg; j++) sum1 += sa1[j * 32 + lane];
        float mvs = xln + xrn + sum1 * invd;
        float lrs = mvs > 0.f ? mvs : 0.2f * mvs;
        float eps_ = lrs * satt[lane];
#pragma unroll
        for (int o = 16; o; o >>= 1) eps_ += __shfl_xor_sync(0xffffffffu, eps_, o);
        float el = (lane < deg) ? se[st + lane] : -1e30f;
        float mx = el;
#pragma unroll
        for (int o = 16; o; o >>= 1) mx = fmaxf(mx, __shfl_xor_sync(0xffffffffu, mx, o));
        mx = fmaxf(mx, eps_);
        float wj = (lane < deg) ? __expf(el - mx) : 0.f;
        float denom = wj;
#pragma unroll
        for (int o = 16; o; o >>= 1) denom += __shfl_xor_sync(0xffffffffu, denom, o);
        float wself = __expf(eps_ - mx);
        denom += wself;
        if (lane < deg) se[st + lane] = wj;
        __syncwarp();
        float acc = wself * xln;
        for (int j = st; j < st + deg; j++) {
            int s = (scsr[j] >> 20) & 31;
            acc += se[j] * sxl[s * 36 + lane];
        }
        float ov = acc / denom + sbo[lane];
        ov = fmaxf(ov, 0.f);
        g_h1[(size_t)(g * P + n) * H1 + lane] = ov;
        st_s += ov; st_q += ov * ov;
    }

    // ---- phase 7: fused BN1 stats
    sred[t] = st_s; __syncthreads();
    if (t < 32) {
        float a = 0.f;
#pragma unroll
        for (int k = 0; k < 8; k++) a += sred[t + 32 * k];
        atomicAdd(&g_sum1[t], (double)a);
    }
    __syncthreads();
    sred[t] = st_q; __syncthreads();
    if (t < 32) {
        float a = 0.f;
#pragma unroll
        for (int k = 0; k < 8; k++) a += sred[t + 32 * k];
        atomicAdd(&g_sq1[t], (double)a);
    }
}

// ============ K3: GATv2 layer 2 ============
__global__ __launch_bounds__(192) void kC(
    const float* __restrict__ Wl2, const float* __restrict__ bl2,
    const float* __restrict__ Wr2, const float* __restrict__ br2,
    const float* __restrict__ att2, const float* __restrict__ bo2,
    const float* __restrict__ g1v, const float* __restrict__ be1)
{
    int g = blockIdx.x;
    int t = threadIdx.x, lane = t & 31;
    int n = t >> 3, l = t & 7;
    unsigned omask = 0xFFu << ((lane >> 3) * 8);

    __shared__ float sh[P * 33];
    __shared__ float sWl[H1 * H2], sWr[H1 * H2];
    __shared__ float sxl[P * 9], sxr[P * 9];
    __shared__ float sa2[CAP * 9];
    __shared__ unsigned scsr[CAP];
    __shared__ float sscale[H1], sbias[H1], satt[H2], sbl[H2], sbr[H2], sbo[H2];
    __shared__ int sdegc[P], sstart[P];
    __shared__ float sred[192];

    if (t < H1) {
        double mu = g_sum1[t] / (double)NN;
        double var = g_sq1[t] / (double)NN - mu * mu;
        float sc = g1v[t] * rsqrtf((float)var + EPSBN);
        sscale[t] = sc;
        sbias[t] = be1[t] - (float)mu * sc;
    }
    for (int i = t; i < H1 * H2; i += 192) { sWl[i] = Wl2[i]; sWr[i] = Wr2[i]; }
    if (t < H2) { satt[t] = att2[t]; sbl[t] = bl2[t]; sbr[t] = br2[t]; sbo[t] = bo2[t]; }
    if (t < P) {
        int d = g_ndeg[g * P + t];
        sdegc[t] = d > BCAP ? BCAP : d;
    }
    __syncthreads();

    // reset g_ndeg for next invocation (after read)
    if (t < P) g_ndeg[g * P + t] = 0;

    int base = g * CAP;
    int m = g_gm[g]; if (m > CAP) m = CAP;

    for (int i = t; i < P * H1; i += 192) {
        int nn = i >> 5, k = i & 31;
        sh[nn * 33 + k] = g_h1[(size_t)g * P * H1 + i] * sscale[k] + sbias[k];
    }
    for (int i = t; i < m; i += 192) scsr[i] = g_csr[base + i];
    for (int i = t; i < m * 2; i += 192) {
        int j = i >> 1, half = i & 1;
        int eid = g_csr[base + j] & 0xFFFFF;
        float4 v = ((const float4*)g_a2)[(size_t)eid * 2 + half];
        sa2[j * 9 + half * 4 + 0] = v.x;
        sa2[j * 9 + half * 4 + 1] = v.y;
        sa2[j * 9 + half * 4 + 2] = v.z;
        sa2[j * 9 + half * 4 + 3] = v.w;
    }
    if (t < 32) {
        int v = (lane < P) ? sdegc[lane] : 0;
        int orig = v;
#pragma unroll
        for (int off = 1; off < 32; off <<= 1) {
            int u = __shfl_up_sync(0xffffffffu, v, off);
            if (lane >= off) v += u;
        }
        if (lane < P) sstart[lane] = v - orig;
    }
    __syncthreads();

    {
        float al = sbl[l], ar = sbr[l];
#pragma unroll
        for (int k = 0; k < H1; k++) {
            float v = sh[n * 33 + k];
            al += v * sWl[k * H2 + l];
            ar += v * sWr[k * H2 + l];
        }
        sxl[n * 9 + l] = al; sxr[n * 9 + l] = ar;
    }
    __syncthreads();

    if (t < m) {
        unsigned pk = scsr[t];
        int s = (pk >> 20) & 31, d = (pk >> 25) & 31;
        float e = 0.f;
#pragma unroll
        for (int k = 0; k < H2; k++) {
            float mv = sxl[s * 9 + k] + sxr[d * 9 + k] + sa2[t * 9 + k];
            float lr = mv > 0.f ? mv : 0.2f * mv;
            e += lr * satt[k];
        }
        sa2[t * 9 + 8] = e;
    }
    __syncthreads();

    int st = sstart[n], deg = sdegc[n];
    float invd = 1.f / fmaxf((float)deg, 1.f);
    float xln = sxl[n * 9 + l], xrn = sxr[n * 9 + l];
    // selfWe2 = (Σ a2_j)/deg  (linearity)
    float selfa2 = 0.f;
    for (int j = st; j < st + deg; j++) selfa2 += sa2[j * 9 + l];
    float mvs = xln + xrn + selfa2 * invd;
    float lrs = mvs > 0.f ? mvs : 0.2f * mvs;
    float eps_ = lrs * satt[l];
    eps_ += __shfl_xor_sync(omask, eps_, 1);
    eps_ += __shfl_xor_sync(omask, eps_, 2);
    eps_ += __shfl_xor_sync(omask, eps_, 4);
    float mx = -1e30f;
    for (int j = st + l; j < st + deg; j += 8) mx = fmaxf(mx, sa2[j * 9 + 8]);
    mx = fmaxf(mx, __shfl_xor_sync(omask, mx, 1));
    mx = fmaxf(mx, __shfl_xor_sync(omask, mx, 2));
    mx = fmaxf(mx, __shfl_xor_sync(omask, mx, 4));
    mx = fmaxf(mx, eps_);
    float denom = 0.f;
    for (int j = st + l; j < st + deg; j += 8) {
        float w = __expf(sa2[j * 9 + 8] - mx);
        sa2[j * 9 + 8] = w;
        denom += w;
    }
    denom += __shfl_xor_sync(omask, denom, 1);
    denom += __shfl_xor_sync(omask, denom, 2);
    denom += __shfl_xor_sync(omask, denom, 4);
    float wself = __expf(eps_ - mx);
    denom += wself;
    __syncwarp();
    float acc = wself * xln;
    for (int j = st; j < st + deg; j++) {
        int s = (scsr[j] >> 20) & 31;
        acc += sa2[j * 9 + 8] * sxl[s * 9 + l];
    }
    float ov = acc / denom + sbo[l];
    ov = 1.f / (1.f + __expf(-ov));
    g_h2[(size_t)g * P * H2 + t] = ov;

    sred[t] = ov; __syncthreads();
    if (t < 8) {
        float a = 0.f;
#pragma unroll
        for (int k = 0; k < 24; k++) a += sred[t + 8 * k];
        atomicAdd(&g_sum2[t], (double)a);
    }
    __syncthreads();
    sred[t] = ov * ov; __syncthreads();
    if (t < 8) {
        float a = 0.f;
#pragma unroll
        for (int k = 0; k < 24; k++) a += sred[t + 8 * k];
        atomicAdd(&g_sq2[t], (double)a);
    }
}

// ============ K4: BN2 + pool + MLP head ============
__global__ __launch_bounds__(256) void kE(
    const float* __restrict__ x,
    const float* __restrict__ g2, const float* __restrict__ be2,
    const float* __restrict__ W1, const float* __restrict__ b1,
    const float* __restrict__ W2, const float* __restrict__ b2,
    const float* __restrict__ W3, const float* __restrict__ b3,
    const float* __restrict__ W4, const float* __restrict__ b4,
    const float* __restrict__ Wo, const float* __restrict__ bo,
    float* __restrict__ out)
{
    int t = threadIdx.x, w = t >> 5, lane = t & 31;
    int g = blockIdx.x * 8 + w;

    __shared__ float sW1[30 * 32], sb1[32], sW2[32 * 16], sb2[16];
    __shared__ float sW3[16 * 8], sb3[8], sW4[8 * 4], sb4[4], sWo[4 * 2], sbo[2];
    __shared__ float sscale[H2], sbias[H2];
    __shared__ float zz[8][90];

    for (int i = t; i < 30 * 32; i += 256) sW1[i] = W1[i];
    for (int i = t; i < 32 * 16; i += 256) sW2[i] = W2[i];
    if (t < 16 * 8) sW3[t] = W3[t];
    if (t < 8 * 4) sW4[t] = W4[t];
    if (t < 8) sWo[t] = Wo[t];
    if (t < 32) sb1[t] = b1[t];
    if (t < 16) sb2[t] = b2[t];
    if (t < 8) sb3[t] = b3[t];
    if (t < 4) sb4[t] = b4[t];
    if (t < 2) sbo[t] = bo[t];
    if (t < H2) {
        double mu = g_sum2[t] / (double)NN;
        double var = g_sq2[t] / (double)NN - mu * mu;
        float sc = g2[t] * rsqrtf((float)var + EPSBN);
        sscale[t] = sc;
        sbias[t] = be2[t] - (float)mu * sc;
    }
    __syncthreads();

    float* z  = zz[w];
    float* z1 = z + 30;
    float* z2 = z1 + 32;
    float* z3 = z2 + 16;
    float* z4 = z3 + 8;

    float acc = 0.f;
    for (int j = lane; j < P * H2; j += 32) {
        int f = j & 7;
        acc += g_h2[(size_t)g * P * H2 + j] * sscale[f] + sbias[f];
    }
    acc += __shfl_xor_sync(0xffffffffu, acc, 8);
    acc += __shfl_xor_sync(0xffffffffu, acc, 16);
    if (lane < 8)  z[lane] = acc * (1.f / 24.f);
    if (lane < 22) z[8 + lane] = x[(size_t)(g * P) * 96 + 74 + lane];
    __syncwarp();

    { float a = sb1[lane];
#pragma unroll
      for (int k = 0; k < 30; k++) a += z[k] * sW1[k * 32 + lane];
      z1[lane] = fmaxf(a, 0.f); }
    __syncwarp();
    if (lane < 16) { float a = sb2[lane];
#pragma unroll
      for (int k = 0; k < 32; k++) a += z1[k] * sW2[k * 16 + lane];
      z2[lane] = fmaxf(a, 0.f); }
    __syncwarp();
    if (lane < 8) { float a = sb3[lane];
#pragma unroll
      for (int k = 0; k < 16; k++) a += z2[k] * sW3[k * 8 + lane];
      z3[lane] = fmaxf(a, 0.f); }
    __syncwarp();
    if (lane < 4) { float a = sb4[lane];
#pragma unroll
      for (int k = 0; k < 8; k++) a += z3[k] * sW4[k * 4 + lane];
      z4[lane] = fmaxf(a, 0.f); }
    __syncwarp();
    if (lane < 2) { float a = sbo[lane];
#pragma unroll
      for (int k = 0; k < 4; k++) a += z4[k] * sWo[k * 2 + lane];
      out[g * 2 + lane] = a; }
}

// ---------------- kReset: clear BN stat accumulators for next run ---------
__global__ void kReset() {
    int t = threadIdx.x;
    if (t < H1) { g_sum1[t] = 0.0; g_sq1[t] = 0.0; }
    if (t < H2) { g_sum2[t] = 0.0; g_sq2[t] = 0.0; }
}

// ---------------- launch ----------------
extern "C" void kernel_launch(void* const* d_in, const int* in_sizes, int n_in,
                              void* d_out, int out_size)
{
    const float* x    = (const float*)d_in[0];
    const int*   ei   = (const int*)  d_in[1];
    const float* ea   = (const float*)d_in[2];
    const float* Wl1  = (const float*)d_in[4];
    const float* bl1  = (const float*)d_in[5];
    const float* Wr1  = (const float*)d_in[6];
    const float* br1  = (const float*)d_in[7];
    const float* We1  = (const float*)d_in[8];
    const float* att1 = (const float*)d_in[9];
    const float* bo1  = (const float*)d_in[10];
    const float* Wl2  = (const float*)d_in[11];
    const float* bl2  = (const float*)d_in[12];
    const float* Wr2  = (const float*)d_in[13];
    const float* br2  = (const float*)d_in[14];
    const float* We2  = (const float*)d_in[15];
    const float* att2 = (const float*)d_in[16];
    const float* bo2  = (const float*)d_in[17];
    const float* g1   = (const float*)d_in[18];
    const float* be1  = (const float*)d_in[19];
    const float* g2   = (const float*)d_in[20];
    const float* be2  = (const float*)d_in[21];
    const float* fc1W = (const float*)d_in[22];
    const float* fc1b = (const float*)d_in[23];
    const float* fc2W = (const float*)d_in[24];
    const float* fc2b = (const float*)d_in[25];
    const float* fc3W = (const float*)d_in[26];
    const float* fc3b = (const float*)d_in[27];
    const float* fc4W = (const float*)d_in[28];
    const float* fc4b = (const float*)d_in[29];
    const float* outW = (const float*)d_in[30];
    const float* outb = (const float*)d_in[31];

    static cudaStream_t s1 = nullptr, s2 = nullptr;
    static cudaEvent_t ev0 = nullptr, ev1 = nullptr, ev2 = nullptr;
    if (s1 == nullptr) {
        cudaStreamCreateWithFlags(&s1, cudaStreamNonBlocking);
        cudaStreamCreateWithFlags(&s2, cudaStreamNonBlocking);
        cudaEventCreateWithFlags(&ev0, cudaEventDisableTiming);
        cudaEventCreateWithFlags(&ev1, cudaEventDisableTiming);
        cudaEventCreateWithFlags(&ev2, cudaEventDisableTiming);
    }

    // fork: side streams join the (possibly captured) main stream
    cudaEventRecord(ev0, 0);
    cudaStreamWaitEvent(s1, ev0, 0);
    cudaStreamWaitEvent(s2, ev0, 0);

    kXlXr<<<NN / 64, 256, 0, s1>>>(x, Wl1, bl1, Wr1, br1);
    cudaEventRecord(ev1, s1);

    kA1A2<<<EE / 128, 256, 0, s2>>>(ea, We1, We2);
    cudaEventRecord(ev2, s2);

    kScatter<<<EE / 256, 256>>>(ei);

    // join
    cudaStreamWaitEvent(0, ev1, 0);
    cudaStreamWaitEvent(0, ev2, 0);

    kA<<<G, 256>>>(att1, bo1);
    kC<<<G, 192>>>(Wl2, bl2, Wr2, br2, att2, bo2, g1, be1);
    kE<<<G / 8, 256>>>(x, g2, be2, fc1W, fc1b, fc2W, fc2b, fc3W, fc3b,
                       fc4W, fc4b, outW, outb, (float*)d_out);
    kReset<<<1, 32>>>();
}

// round 11
// speedup vs baseline: 1.3000x; 1.3000x over previous
#include <cuda_runtime.h>
#include <cstdint>

#define G    8192
#define P    24
#define NN   (G*P)          // 196608
#define EE   (NN*4)         // 786432
#define FIN  74
#define H1   32
#define H2   8
#define CAP  152            // per-group edge capacity (m == 96 exactly)
#define BCAP 32             // per-node bucket capacity
#define EPSBN 1e-5f

// ---------------- scratch ----------------
__device__ int      g_ndeg[NN];                    // zero-init; kC resets
__device__ unsigned g_bucket[(size_t)NN * BCAP];   // eid | s_loc<<20
__device__ unsigned g_csr[G * CAP];
__device__ int      g_gm[G];
__device__ float    g_xl[(size_t)NN * H1];
__device__ float    g_xr[(size_t)NN * H1];
__device__ float    g_e[EE];                       // per-edge layer-1 logit
__device__ float    g_a2[(size_t)EE * H2];         // ea@We2, edge order
__device__ float    g_h1[(size_t)NN * H1];
__device__ float    g_h2[(size_t)NN * H2];
__device__ double   g_sum1[H1], g_sq1[H1], g_sum2[H2], g_sq2[H2]; // kReset

// ---------------- K1: scatter into per-dst-node buckets ----------------
__global__ void kScatter(const int* __restrict__ ei) {
    int e = blockIdx.x * blockDim.x + threadIdx.x;
    if (e >= EE) return;
    int s = ei[e], d = ei[EE + e];
    int pos = atomicAdd(&g_ndeg[d], 1);
    if (pos < BCAP)
        g_bucket[(size_t)d * BCAP + pos] = (unsigned)e | ((unsigned)(s % P) << 20);
}

// ============ dense node GEMV — float4 k-blocked ============
__global__ __launch_bounds__(256) void kXlXr(
    const float* __restrict__ x,
    const float* __restrict__ Wl1, const float* __restrict__ bl1,
    const float* __restrict__ Wr1, const float* __restrict__ br1)
{
    __shared__ float2 sW[FIN * H1];
    __shared__ float  sx[64 * 76];
    int t = threadIdx.x, lane = t & 31, wid = t >> 5;
    int n0 = blockIdx.x * 64;

    for (int i = t; i < FIN * H1; i += 256)
        sW[i] = make_float2(Wl1[i], Wr1[i]);
    for (int i = t; i < 64 * 19; i += 256) {
        int r = i / 19, q = i - r * 19;
        ((float4*)(sx + r * 76))[q] = ((const float4*)(x + (size_t)(n0 + r) * 96))[q];
    }
    __syncthreads();

    float bl = bl1[lane], br = br1[lane];
    float al[8], ar[8];
#pragma unroll
    for (int n = 0; n < 8; n++) { al[n] = bl; ar[n] = br; }

    const float* xbase = sx + wid * 8 * 76;
#pragma unroll 1
    for (int k4 = 0; k4 < 18; k4++) {
        int k = k4 * 4;
        float2 w0 = sW[(k + 0) * H1 + lane];
        float2 w1 = sW[(k + 1) * H1 + lane];
        float2 w2 = sW[(k + 2) * H1 + lane];
        float2 w3 = sW[(k + 3) * H1 + lane];
#pragma unroll
        for (int n = 0; n < 8; n++) {
            float4 xv = *(const float4*)(xbase + n * 76 + k);
            al[n] += xv.x * w0.x + xv.y * w1.x + xv.z * w2.x + xv.w * w3.x;
            ar[n] += xv.x * w0.y + xv.y * w1.y + xv.z * w2.y + xv.w * w3.y;
        }
    }
    {
        float2 w0 = sW[72 * H1 + lane];
        float2 w1 = sW[73 * H1 + lane];
#pragma unroll
        for (int n = 0; n < 8; n++) {
            float2 xv = *(const float2*)(xbase + n * 76 + 72);
            al[n] += xv.x * w0.x + xv.y * w1.x;
            ar[n] += xv.x * w0.y + xv.y * w1.y;
        }
    }
#pragma unroll
    for (int n = 0; n < 8; n++) {
        size_t idx = (size_t)(n0 + wid * 8 + n) * H1 + lane;
        g_xl[idx] = al[n];
        g_xr[idx] = ar[n];
    }
}

// ============ dense edge kernel: logit scalar + a2 (edge order) ===========
__global__ __launch_bounds__(256) void kEdge(
    const float* __restrict__ ea, const int* __restrict__ ei,
    const float* __restrict__ We1, const float* __restrict__ We2,
    const float* __restrict__ att1)
{
    __shared__ float sea[128 * 16];
    __shared__ float sW[16 * 40];     // [k][40]: 0..31 We1, 32..39 We2
    __shared__ float satt[H1];
    int t = threadIdx.x;
    int e0 = blockIdx.x * 128;

    for (int i = t; i < 512; i += 256)
        ((float4*)sea)[i] = ((const float4*)ea)[(size_t)e0 * 4 + i];
    for (int i = t; i < 16 * 40; i += 256) {
        int k = i / 40, o = i - k * 40;
        sW[i] = (o < 32) ? We1[k * 32 + o] : We2[k * 8 + (o - 32)];
    }
    if (t < H1) satt[t] = att1[t];
    __syncthreads();

    int e = t >> 1, h = t & 1;            // 2 threads/edge, 5 quads each
    const float4* W4 = (const float4*)sW; // [k][10]
    float4 acc[5];
#pragma unroll
    for (int c = 0; c < 5; c++) acc[c] = make_float4(0.f, 0.f, 0.f, 0.f);
#pragma unroll
    for (int k = 0; k < 16; k++) {
        float evk = sea[e * 16 + k];
#pragma unroll
        for (int c = 0; c < 5; c++) {
            float4 w = W4[k * 10 + h * 5 + c];
            acc[c].x += evk * w.x; acc[c].y += evk * w.y;
            acc[c].z += evk * w.z; acc[c].w += evk * w.w;
        }
    }
    int eg = e0 + e;
    int s = ei[eg], d = ei[EE + eg];
    float part = 0.f;
#pragma unroll
    for (int c = 0; c < 5; c++) {
        int q = h * 5 + c;
        if (q < 8) {
            float4 xlq = ((const float4*)g_xl)[(size_t)s * 8 + q];
            float4 xrq = ((const float4*)g_xr)[(size_t)d * 8 + q];
            float4 at  = ((const float4*)satt)[q];
            float m0 = xlq.x + xrq.x + acc[c].x;
            float m1 = xlq.y + xrq.y + acc[c].y;
            float m2 = xlq.z + xrq.z + acc[c].z;
            float m3 = xlq.w + xrq.w + acc[c].w;
            part += (m0 > 0.f ? m0 : 0.2f * m0) * at.x
                  + (m1 > 0.f ? m1 : 0.2f * m1) * at.y
                  + (m2 > 0.f ? m2 : 0.2f * m2) * at.z
                  + (m3 > 0.f ? m3 : 0.2f * m3) * at.w;
        }
    }
    part += __shfl_xor_sync(0xffffffffu, part, 1);
    if (h == 0) {
        g_e[eg] = part;
    } else {
        ((float4*)g_a2)[(size_t)eg * 2 + 0] = acc[3];   // q=8
        ((float4*)g_a2)[(size_t)eg * 2 + 1] = acc[4];   // q=9
    }
}

// ============ K2: GATv2 layer 1 — softmax + aggregate only ============
__global__ __launch_bounds__(256, 6) void kA(
    const float* __restrict__ ea,
    const float* __restrict__ We1,
    const float* __restrict__ att1, const float* __restrict__ bo1)
{
    int g = blockIdx.x;
    int t = threadIdx.x, lane = t & 31, wid = t >> 5;

    __shared__ float sWe1[16 * H1];
    __shared__ float satt[H1], sbo[H1];
    __shared__ float sxl[P * 36], sxr[P * 36];
    __shared__ float ssumEA[P * 16];
    __shared__ float se[CAP];
    __shared__ unsigned scsr[CAP];
    __shared__ int sdegc[P], sstart[P], sm_m[1];
    __shared__ float sred[256];

    // ---- phase 1: loads
    for (int i = t; i < 16 * H1; i += 256) sWe1[i] = We1[i];
    if (t < H1) { satt[t] = att1[t]; sbo[t] = bo1[t]; }
    for (int i = t; i < P * H1 / 4; i += 256) {
        int n = i >> 3, q = i & 7;
        ((float4*)(sxl + n * 36))[q] = ((const float4*)(g_xl + (size_t)g * P * H1))[i];
        ((float4*)(sxr + n * 36))[q] = ((const float4*)(g_xr + (size_t)g * P * H1))[i];
    }
    if (t < P) {
        int d = g_ndeg[g * P + t];
        sdegc[t] = d > BCAP ? BCAP : d;
    }
    for (int i = t; i < P * 16; i += 256) ssumEA[i] = 0.f;
    __syncthreads();

    // ---- phase 2: warp-scan CSR starts
    if (wid == 0) {
        int v = (lane < P) ? sdegc[lane] : 0;
        int orig = v;
#pragma unroll
        for (int off = 1; off < 32; off <<= 1) {
            int u = __shfl_up_sync(0xffffffffu, v, off);
            if (lane >= off) v += u;
        }
        if (lane < P) sstart[lane] = v - orig;
        if (lane == P - 1) { sm_m[0] = v; g_gm[g] = v; }
    }
    __syncthreads();

    int base = g * CAP;
    int m = sm_m[0]; if (m > CAP) m = CAP;

    // ---- phase 3: compact copy from node buckets
    for (int n = wid; n < P; n += 8) {
        int deg = sdegc[n], st = sstart[n];
        if (lane < deg) {
            unsigned pk = g_bucket[(size_t)(g * P + n) * BCAP + lane]
                        | ((unsigned)n << 25);
            scsr[st + lane] = pk;
            g_csr[base + st + lane] = pk;
        }
    }
    __syncthreads();

    // ---- phase 4: gather logits + accumulate sumEA
    for (int i = t; i < m; i += 256)
        se[i] = g_e[scsr[i] & 0xFFFFF];
    for (int idx = t; idx < m * 16; idx += 256) {
        int j = idx >> 4, k = idx & 15;
        unsigned pk = scsr[j];
        int eid = pk & 0xFFFFF, d = (pk >> 25) & 31;
        atomicAdd(&ssumEA[d * 16 + k], ea[(size_t)eid * 16 + k]);
    }
    __syncthreads();

    // ---- phase 5: per-node softmax + aggregation (warp per node)
    float st_s = 0.f, st_q = 0.f;
    for (int n = wid; n < P; n += 8) {
        int st = sstart[n], deg = sdegc[n];
        float invd = 1.f / fmaxf((float)deg, 1.f);
        float xln = sxl[n * 36 + lane], xrn = sxr[n * 36 + lane];
        // self logit: sum1 = (Σ ea) @ We1
        float sum1 = 0.f;
#pragma unroll
        for (int k = 0; k < 16; k++)
            sum1 += ssumEA[n * 16 + k] * sWe1[k * H1 + lane];
        float mvs = xln + xrn + sum1 * invd;
        float lrs = mvs > 0.f ? mvs : 0.2f * mvs;
        float eps_ = lrs * satt[lane];
#pragma unroll
        for (int o = 16; o; o >>= 1) eps_ += __shfl_xor_sync(0xffffffffu, eps_, o);
        float el = (lane < deg) ? se[st + lane] : -1e30f;
        float mx = el;
#pragma unroll
        for (int o = 16; o; o >>= 1) mx = fmaxf(mx, __shfl_xor_sync(0xffffffffu, mx, o));
        mx = fmaxf(mx, eps_);
        float wj = (lane < deg) ? __expf(el - mx) : 0.f;
        float denom = wj;
#pragma unroll
        for (int o = 16; o; o >>= 1) denom += __shfl_xor_sync(0xffffffffu, denom, o);
        float wself = __expf(eps_ - mx);
        denom += wself;
        if (lane < deg) se[st + lane] = wj;
        __syncwarp();
        float acc = wself * xln;
        for (int j = st; j < st + deg; j++) {
            int s = (scsr[j] >> 20) & 31;
            acc += se[j] * sxl[s * 36 + lane];
        }
        float ov = acc / denom + sbo[lane];
        ov = fmaxf(ov, 0.f);
        g_h1[(size_t)(g * P + n) * H1 + lane] = ov;
        st_s += ov; st_q += ov * ov;
    }

    // ---- phase 6: fused BN1 stats
    sred[t] = st_s; __syncthreads();
    if (t < 32) {
        float a = 0.f;
#pragma unroll
        for (int k = 0; k < 8; k++) a += sred[t + 32 * k];
        atomicAdd(&g_sum1[t], (double)a);
    }
    __syncthreads();
    sred[t] = st_q; __syncthreads();
    if (t < 32) {
        float a = 0.f;
#pragma unroll
        for (int k = 0; k < 8; k++) a += sred[t + 32 * k];
        atomicAdd(&g_sq1[t], (double)a);
    }
}

// ============ K3: GATv2 layer 2 ============
__global__ __launch_bounds__(192) void kC(
    const float* __restrict__ Wl2, const float* __restrict__ bl2,
    const float* __restrict__ Wr2, const float* __restrict__ br2,
    const float* __restrict__ att2, const float* __restrict__ bo2,
    const float* __restrict__ g1v, const float* __restrict__ be1)
{
    int g = blockIdx.x;
    int t = threadIdx.x, lane = t & 31;
    int n = t >> 3, l = t & 7;
    unsigned omask = 0xFFu << ((lane >> 3) * 8);

    __shared__ float sh[P * 33];
    __shared__ float sWl[H1 * H2], sWr[H1 * H2];
    __shared__ float sxl[P * 9], sxr[P * 9];
    __shared__ float sa2[CAP * 9];
    __shared__ unsigned scsr[CAP];
    __shared__ float sscale[H1], sbias[H1], satt[H2], sbl[H2], sbr[H2], sbo[H2];
    __shared__ int sdegc[P], sstart[P];
    __shared__ float sred[192];

    if (t < H1) {
        double mu = g_sum1[t] / (double)NN;
        double var = g_sq1[t] / (double)NN - mu * mu;
        float sc = g1v[t] * rsqrtf((float)var + EPSBN);
        sscale[t] = sc;
        sbias[t] = be1[t] - (float)mu * sc;
    }
    for (int i = t; i < H1 * H2; i += 192) { sWl[i] = Wl2[i]; sWr[i] = Wr2[i]; }
    if (t < H2) { satt[t] = att2[t]; sbl[t] = bl2[t]; sbr[t] = br2[t]; sbo[t] = bo2[t]; }
    if (t < P) {
        int d = g_ndeg[g * P + t];
        sdegc[t] = d > BCAP ? BCAP : d;
    }
    __syncthreads();

    // reset g_ndeg for next invocation (after read)
    if (t < P) g_ndeg[g * P + t] = 0;

    int base = g * CAP;
    int m = g_gm[g]; if (m > CAP) m = CAP;

    for (int i = t; i < P * H1; i += 192) {
        int nn = i >> 5, k = i & 31;
        sh[nn * 33 + k] = g_h1[(size_t)g * P * H1 + i] * sscale[k] + sbias[k];
    }
    for (int i = t; i < m; i += 192) scsr[i] = g_csr[base + i];
    for (int i = t; i < m * 2; i += 192) {
        int j = i >> 1, half = i & 1;
        int eid = g_csr[base + j] & 0xFFFFF;
        float4 v = ((const float4*)g_a2)[(size_t)eid * 2 + half];
        sa2[j * 9 + half * 4 + 0] = v.x;
        sa2[j * 9 + half * 4 + 1] = v.y;
        sa2[j * 9 + half * 4 + 2] = v.z;
        sa2[j * 9 + half * 4 + 3] = v.w;
    }
    if (t < 32) {
        int v = (lane < P) ? sdegc[lane] : 0;
        int orig = v;
#pragma unroll
        for (int off = 1; off < 32; off <<= 1) {
            int u = __shfl_up_sync(0xffffffffu, v, off);
            if (lane >= off) v += u;
        }
        if (lane < P) sstart[lane] = v - orig;
    }
    __syncthreads();

    {
        float al = sbl[l], ar = sbr[l];
#pragma unroll
        for (int k = 0; k < H1; k++) {
            float v = sh[n * 33 + k];
            al += v * sWl[k * H2 + l];
            ar += v * sWr[k * H2 + l];
        }
        sxl[n * 9 + l] = al; sxr[n * 9 + l] = ar;
    }
    __syncthreads();

    if (t < m) {
        unsigned pk = scsr[t];
        int s = (pk >> 20) & 31, d = (pk >> 25) & 31;
        float e = 0.f;
#pragma unroll
        for (int k = 0; k < H2; k++) {
            float mv = sxl[s * 9 + k] + sxr[d * 9 + k] + sa2[t * 9 + k];
            float lr = mv > 0.f ? mv : 0.2f * mv;
            e += lr * satt[k];
        }
        sa2[t * 9 + 8] = e;
    }
    __syncthreads();

    int st = sstart[n], deg = sdegc[n];
    float invd = 1.f / fmaxf((float)deg, 1.f);
    float xln = sxl[n * 9 + l], xrn = sxr[n * 9 + l];
    float selfa2 = 0.f;
    for (int j = st; j < st + deg; j++) selfa2 += sa2[j * 9 + l];
    float mvs = xln + xrn + selfa2 * invd;
    float lrs = mvs > 0.f ? mvs : 0.2f * mvs;
    float eps_ = lrs * satt[l];
    eps_ += __shfl_xor_sync(omask, eps_, 1);
    eps_ += __shfl_xor_sync(omask, eps_, 2);
    eps_ += __shfl_xor_sync(omask, eps_, 4);
    float mx = -1e30f;
    for (int j = st + l; j < st + deg; j += 8) mx = fmaxf(mx, sa2[j * 9 + 8]);
    mx = fmaxf(mx, __shfl_xor_sync(omask, mx, 1));
    mx = fmaxf(mx, __shfl_xor_sync(omask, mx, 2));
    mx = fmaxf(mx, __shfl_xor_sync(omask, mx, 4));
    mx = fmaxf(mx, eps_);
    float denom = 0.f;
    for (int j = st + l; j < st + deg; j += 8) {
        float w = __expf(sa2[j * 9 + 8] - mx);
        sa2[j * 9 + 8] = w;
        denom += w;
    }
    denom += __shfl_xor_sync(omask, denom, 1);
    denom += __shfl_xor_sync(omask, denom, 2);
    denom += __shfl_xor_sync(omask, denom, 4);
    float wself = __expf(eps_ - mx);
    denom += wself;
    __syncwarp();
    float acc = wself * xln;
    for (int j = st; j < st + deg; j++) {
        int s = (scsr[j] >> 20) & 31;
        acc += sa2[j * 9 + 8] * sxl[s * 9 + l];
    }
    float ov = acc / denom + sbo[l];
    ov = 1.f / (1.f + __expf(-ov));
    g_h2[(size_t)g * P * H2 + t] = ov;

    sred[t] = ov; __syncthreads();
    if (t < 8) {
        float a = 0.f;
#pragma unroll
        for (int k = 0; k < 24; k++) a += sred[t + 8 * k];
        atomicAdd(&g_sum2[t], (double)a);
    }
    __syncthreads();
    sred[t] = ov * ov; __syncthreads();
    if (t < 8) {
        float a = 0.f;
#pragma unroll
        for (int k = 0; k < 24; k++) a += sred[t + 8 * k];
        atomicAdd(&g_sq2[t], (double)a);
    }
}

// ============ K4: BN2 + pool + MLP head ============
__global__ __launch_bounds__(256) void kE(
    const float* __restrict__ x,
    const float* __restrict__ g2, const float* __restrict__ be2,
    const float* __restrict__ W1, const float* __restrict__ b1,
    const float* __restrict__ W2, const float* __restrict__ b2,
    const float* __restrict__ W3, const float* __restrict__ b3,
    const float* __restrict__ W4, const float* __restrict__ b4,
    const float* __restrict__ Wo, const float* __restrict__ bo,
    float* __restrict__ out)
{
    int t = threadIdx.x, w = t >> 5, lane = t & 31;
    int g = blockIdx.x * 8 + w;

    __shared__ float sW1[30 * 32], sb1[32], sW2[32 * 16], sb2[16];
    __shared__ float sW3[16 * 8], sb3[8], sW4[8 * 4], sb4[4], sWo[4 * 2], sbo[2];
    __shared__ float sscale[H2], sbias[H2];
    __shared__ float zz[8][90];

    for (int i = t; i < 30 * 32; i += 256) sW1[i] = W1[i];
    for (int i = t; i < 32 * 16; i += 256) sW2[i] = W2[i];
    if (t < 16 * 8) sW3[t] = W3[t];
    if (t < 8 * 4) sW4[t] = W4[t];
    if (t < 8) sWo[t] = Wo[t];
    if (t < 32) sb1[t] = b1[t];
    if (t < 16) sb2[t] = b2[t];
    if (t < 8) sb3[t] = b3[t];
    if (t < 4) sb4[t] = b4[t];
    if (t < 2) sbo[t] = bo[t];
    if (t < H2) {
        double mu = g_sum2[t] / (double)NN;
        double var = g_sq2[t] / (double)NN - mu * mu;
        float sc = g2[t] * rsqrtf((float)var + EPSBN);
        sscale[t] = sc;
        sbias[t] = be2[t] - (float)mu * sc;
    }
    __syncthreads();

    float* z  = zz[w];
    float* z1 = z + 30;
    float* z2 = z1 + 32;
    float* z3 = z2 + 16;
    float* z4 = z3 + 8;

    float acc = 0.f;
    for (int j = lane; j < P * H2; j += 32) {
        int f = j & 7;
        acc += g_h2[(size_t)g * P * H2 + j] * sscale[f] + sbias[f];
    }
    acc += __shfl_xor_sync(0xffffffffu, acc, 8);
    acc += __shfl_xor_sync(0xffffffffu, acc, 16);
    if (lane < 8)  z[lane] = acc * (1.f / 24.f);
    if (lane < 22) z[8 + lane] = x[(size_t)(g * P) * 96 + 74 + lane];
    __syncwarp();

    { float a = sb1[lane];
#pragma unroll
      for (int k = 0; k < 30; k++) a += z[k] * sW1[k * 32 + lane];
      z1[lane] = fmaxf(a, 0.f); }
    __syncwarp();
    if (lane < 16) { float a = sb2[lane];
#pragma unroll
      for (int k = 0; k < 32; k++) a += z1[k] * sW2[k * 16 + lane];
      z2[lane] = fmaxf(a, 0.f); }
    __syncwarp();
    if (lane < 8) { float a = sb3[lane];
#pragma unroll
      for (int k = 0; k < 16; k++) a += z2[k] * sW3[k * 8 + lane];
      z3[lane] = fmaxf(a, 0.f); }
    __syncwarp();
    if (lane < 4) { float a = sb4[lane];
#pragma unroll
      for (int k = 0; k < 8; k++) a += z3[k] * sW4[k * 4 + lane];
      z4[lane] = fmaxf(a, 0.f); }
    __syncwarp();
    if (lane < 2) { float a = sbo[lane];
#pragma unroll
      for (int k = 0; k < 4; k++) a += z4[k] * sWo[k * 2 + lane];
      out[g * 2 + lane] = a; }
}

// ---------------- kReset: clear BN stat accumulators ----------------
__global__ void kReset() {
    int t = threadIdx.x;
    if (t < H1) { g_sum1[t] = 0.0; g_sq1[t] = 0.0; }
    if (t < H2) { g_sum2[t] = 0.0; g_sq2[t] = 0.0; }
}

// ---------------- launch (single stream) ----------------
extern "C" void kernel_launch(void* const* d_in, const int* in_sizes, int n_in,
                              void* d_out, int out_size)
{
    const float* x    = (const float*)d_in[0];
    const int*   ei   = (const int*)  d_in[1];
    const float* ea   = (const float*)d_in[2];
    const float* Wl1  = (const float*)d_in[4];
    const float* bl1  = (const float*)d_in[5];
    const float* Wr1  = (const float*)d_in[6];
    const float* br1  = (const float*)d_in[7];
    const float* We1  = (const float*)d_in[8];
    const float* att1 = (const float*)d_in[9];
    const float* bo1  = (const float*)d_in[10];
    const float* Wl2  = (const float*)d_in[11];
    const float* bl2  = (const float*)d_in[12];
    const float* Wr2  = (const float*)d_in[13];
    const float* br2  = (const float*)d_in[14];
    const float* We2  = (const float*)d_in[15];
    const float* att2 = (const float*)d_in[16];
    const float* bo2  = (const float*)d_in[17];
    const float* g1   = (const float*)d_in[18];
    const float* be1  = (const float*)d_in[19];
    const float* g2   = (const float*)d_in[20];
    const float* be2  = (const float*)d_in[21];
    const float* fc1W = (const float*)d_in[22];
    const float* fc1b = (const float*)d_in[23];
    const float* fc2W = (const float*)d_in[24];
    const float* fc2b = (const float*)d_in[25];
    const float* fc3W = (const float*)d_in[26];
    const float* fc3b = (const float*)d_in[27];
    const float* fc4W = (const float*)d_in[28];
    const float* fc4b = (const float*)d_in[29];
    const float* outW = (const float*)d_in[30];
    const float* outb = (const float*)d_in[31];

    kScatter<<<EE / 256, 256>>>(ei);
    kXlXr<<<NN / 64, 256>>>(x, Wl1, bl1, Wr1, br1);
    kEdge<<<EE / 128, 256>>>(ea, ei, We1, We2, att1);
    kA<<<G, 256>>>(ea, We1, att1, bo1);
    kC<<<G, 192>>>(Wl2, bl2, Wr2, br2, att2, bo2, g1, be1);
    kE<<<G / 8, 256>>>(x, g2, be2, fc1W, fc1b, fc2W, fc2b, fc3W, fc3b,
                       fc4W, fc4b, outW, outb, (float*)d_out);
    kReset<<<1, 32>>>();
}